// round 8
// baseline (speedup 1.0000x reference)
#include <cuda_runtime.h>
#include <cuda_bf16.h>

// LIF neuron: x_seq (T=64, B=32, F=8192) fp32 -> (spike_seq, mem_seq) each (T,B,F).
// R7 -> R8: L2-residency hints are dead (persisting-L2 carveout is 0 and device
// limits are locked). All variants sit at ~5.35 TB/s sustained DRAM on a
// 1R:2W mix. New lever: sm_103's 256-bit global accesses (v8.b32) -- each warp
// instruction covers 1KB contiguous, halving store-issue cost and L1tex
// wavefronts, denser bursts into L2/DRAM write combining.

static constexpr int T  = 64;
static constexpr int BF = 32 * 8192;      // 262144 floats per timestep
static constexpr int N8 = BF / 8;         // 32768 v8 lanes
static constexpr int PF = 4;              // outstanding 256-bit loads per thread

__device__ __forceinline__ void ldg_v8(const float* p, unsigned* r) {
    asm volatile("ld.global.nc.v8.b32 {%0,%1,%2,%3,%4,%5,%6,%7}, [%8];"
        : "=r"(r[0]), "=r"(r[1]), "=r"(r[2]), "=r"(r[3]),
          "=r"(r[4]), "=r"(r[5]), "=r"(r[6]), "=r"(r[7])
        : "l"(p));
}

__device__ __forceinline__ void stg_v8(float* p, const unsigned* r) {
    asm volatile("st.global.v8.b32 [%0], {%1,%2,%3,%4,%5,%6,%7,%8};"
        :: "l"(p),
           "r"(r[0]), "r"(r[1]), "r"(r[2]), "r"(r[3]),
           "r"(r[4]), "r"(r[5]), "r"(r[6]), "r"(r[7])
        : "memory");
}

__global__ __launch_bounds__(32) void lif_kernel(
    const float* __restrict__ x,      // [T, BF]
    float*       __restrict__ out)    // [2, T, BF] : spike then mem
{
    const int lane8 = blockIdx.x * 32 + threadIdx.x;   // v8 lane
    const size_t base = (size_t)lane8 * 8;

    float* spike_out = out;
    float* mem_out   = out + (size_t)T * BF;

    // Prime the prefetch ring: PF 256-bit loads in flight.
    unsigned buf[PF][8];
    #pragma unroll
    for (int i = 0; i < PF; i++)
        ldg_v8(&x[(size_t)i * BF + base], buf[i]);

    float mem[8];
    #pragma unroll
    for (int j = 0; j < 8; j++) mem[j] = 0.0f;

    #pragma unroll
    for (int t = 0; t < T; t++) {
        unsigned xv[8];
        #pragma unroll
        for (int j = 0; j < 8; j++) xv[j] = buf[t & (PF - 1)][j];

        if (t + PF < T)
            ldg_v8(&x[(size_t)(t + PF) * BF + base], buf[t & (PF - 1)]);

        unsigned s[8], m[8];
        #pragma unroll
        for (int j = 0; j < 8; j++) {
            // mem = mem*0.5 + x  (*0.5 exact -> fma bit-matches mul+add)
            mem[j] = __fmaf_rn(mem[j], 0.5f, __uint_as_float(xv[j]));
            const bool spike = (mem[j] >= 1.0f);
            s[j] = spike ? 0x3f800000u : 0u;      // 1.0f : 0.0f
            mem[j] = spike ? 0.0f : mem[j];       // reset (V_RESET = 0)
            m[j] = __float_as_uint(mem[j]);
        }

        stg_v8(&spike_out[(size_t)t * BF + base], s);
        stg_v8(&mem_out  [(size_t)t * BF + base], m);
    }
}

extern "C" void kernel_launch(void* const* d_in, const int* in_sizes, int n_in,
                              void* d_out, int out_size) {
    const float* x = reinterpret_cast<const float*>(d_in[0]);
    float* out = reinterpret_cast<float*>(d_out);

    const int threads = 32;
    const int blocks  = N8 / threads;   // 1024 blocks
    lif_kernel<<<blocks, threads>>>(x, out);
}